// round 5
// baseline (speedup 1.0000x reference)
#include <cuda_runtime.h>
#include <cuda_bf16.h>

#define NN 100000
#define EE 1600000
#define GG 2000
#define HH 128
#define LL 3
#define SCAN_B 512
#define SCAN_NB ((NN + SCAN_B - 1) / SCAN_B)   // 196
#define PITCH 132                              // padded smem row pitch (floats)

// Scratch (__device__ globals; no allocations allowed)
__device__ float g_h [NN * HH];
__device__ float g_h2[NN * HH];
__device__ float g_m [NN * HH];
__device__ int   g_off[NN + 1];
__device__ int   g_cur[NN];
__device__ int   g_csr[EE];
__device__ int   g_bsum[256];
__device__ int   g_bpre[256];
__device__ float g_gsum[GG * HH];
__device__ int   g_gcnt[GG];

// ---------------------------------------------------------------------------
// h = x @ proj_w + proj_b   ([N,4] @ [4,128])
__global__ void proj_kernel(const float* __restrict__ x,
                            const float* __restrict__ pw,
                            const float* __restrict__ pb,
                            float* __restrict__ h) {
    int n = blockIdx.x;
    int j = threadIdx.x;
    const float* xr = x + (size_t)n * 4;
    float acc = pb[j];
    acc += xr[0] * pw[0 * HH + j];
    acc += xr[1] * pw[1 * HH + j];
    acc += xr[2] * pw[2 * HH + j];
    acc += xr[3] * pw[3 * HH + j];
    h[(size_t)n * HH + j] = acc;
}

// ---------------------------------------------------------------------------
// zero deg (stored in g_off during build) + pool buffers
__global__ void zero_kernel(int* __restrict__ deg,
                            float* __restrict__ gsum, int* __restrict__ gcnt) {
    int i = blockIdx.x * blockDim.x + threadIdx.x;
    if (i <= NN) deg[i] = 0;
    if (i < GG * HH) gsum[i] = 0.f;
    if (i < GG) gcnt[i] = 0;
}

__global__ void hist_kernel(const int* __restrict__ ei, int* __restrict__ deg) {
    int e = blockIdx.x * blockDim.x + threadIdx.x;
    if (e < EE) atomicAdd(deg + __ldg(ei + EE + e), 1);
}

// per-block exclusive scan + block totals (deg lives in off[])
__global__ void scan1_kernel(int* __restrict__ off, int* __restrict__ bsum) {
    __shared__ int s[SCAN_B];
    int t = threadIdx.x;
    int i = blockIdx.x * SCAN_B + t;
    int v = (i < NN) ? off[i] : 0;
    s[t] = v;
    __syncthreads();
    for (int o = 1; o < SCAN_B; o <<= 1) {
        int x = (t >= o) ? s[t - o] : 0;
        __syncthreads();
        s[t] += x;
        __syncthreads();
    }
    if (i < NN) off[i] = s[t] - v;            // exclusive within block
    if (t == SCAN_B - 1) bsum[blockIdx.x] = s[t];
}

__global__ void scan2_kernel(const int* __restrict__ bsum, int* __restrict__ bpre) {
    __shared__ int s[256];
    int t = threadIdx.x;
    int v = (t < SCAN_NB) ? bsum[t] : 0;
    s[t] = v;
    __syncthreads();
    for (int o = 1; o < 256; o <<= 1) {
        int x = (t >= o) ? s[t - o] : 0;
        __syncthreads();
        s[t] += x;
        __syncthreads();
    }
    if (t < SCAN_NB) bpre[t] = s[t] - v;
}

__global__ void scan3_kernel(int* __restrict__ off, const int* __restrict__ bpre,
                             int* __restrict__ cur) {
    int i = blockIdx.x * blockDim.x + threadIdx.x;
    if (i < NN) {
        int o = off[i] + bpre[i / SCAN_B];
        off[i] = o;
        cur[i] = o;
    }
    if (i == NN) off[NN] = EE;
}

__global__ void fill_kernel(const int* __restrict__ ei,
                            int* __restrict__ cur, int* __restrict__ csr) {
    int e = blockIdx.x * blockDim.x + threadIdx.x;
    if (e < EE) {
        int s = __ldg(ei + e);
        int d = __ldg(ei + EE + e);
        int p = atomicAdd(cur + d, 1);
        csr[p] = s;
    }
}

// ---------------------------------------------------------------------------
// gather: m[n] = in[n] + sum_{s in nbr(n)} in[s].  One warp per node.
// Lane l owns float4 chunk l of the 128-float row. m streamed (write-once).
__global__ void __launch_bounds__(256) gather_kernel(
    const float* __restrict__ in, float* __restrict__ m,
    const int* __restrict__ off, const int* __restrict__ csr) {
    int n = (blockIdx.x * blockDim.x + threadIdx.x) >> 5;
    if (n >= NN) return;
    int lane = threadIdx.x & 31;
    const float4* in4 = (const float4*)in;

    float4 a = __ldg(in4 + (size_t)n * 32 + lane);
    int e0 = __ldg(off + n);
    int e1 = __ldg(off + n + 1);
#pragma unroll 4
    for (int e = e0; e < e1; e++) {
        int s = __ldg(csr + e);
        float4 v = __ldg(in4 + (size_t)s * 32 + lane);
        a.x += v.x; a.y += v.y; a.z += v.z; a.w += v.w;
    }
    __stcs((float4*)m + (size_t)n * 32 + lane, a);
}

// ---------------------------------------------------------------------------
// h_out = relu( relu(m @ W1 + b1) @ W2 + b2 )
// 64-row tile, 256 threads; thread (rb=tid>>4, cg=(tid&15)*8) owns rows
// rb+16i (i<4), cols cg..cg+7 -> acc[4][8].
// smem: 64 x PITCH tile (padded, conflict-free) + 16x128 W chunk.
__global__ void __launch_bounds__(256) mlp_kernel(
    const float* __restrict__ m_in, float* __restrict__ h_out,
    const float* __restrict__ W1, const float* __restrict__ B1,
    const float* __restrict__ W2, const float* __restrict__ B2) {
    __shared__ float sMT[64 * PITCH];
    __shared__ float sW[16 * HH];

    int tid  = threadIdx.x;
    int row0 = blockIdx.x * 64;

    // load m tile (streamed; zero-pad OOB rows)
    for (int i = tid; i < 64 * 32; i += 256) {
        int r = i >> 5, c = i & 31;
        int gr = row0 + r;
        float4 v = make_float4(0.f, 0.f, 0.f, 0.f);
        if (gr < NN) v = __ldcs((const float4*)(m_in + (size_t)gr * HH) + c);
        *(float4*)(sMT + r * PITCH + c * 4) = v;
    }

    int rb = tid >> 4;            // 0..15
    int cg = (tid & 15) * 8;      // 0..120 step 8

    float acc[4][8];
#pragma unroll
    for (int i = 0; i < 4; i++)
#pragma unroll
        for (int j = 0; j < 8; j++) acc[i][j] = 0.f;

    // ---- GEMM 1: t = m @ W1 ----
    for (int kc = 0; kc < HH; kc += 16) {
        __syncthreads();
        for (int i = tid; i < 16 * 32; i += 256)
            ((float4*)sW)[i] = ((const float4*)(W1 + (size_t)kc * HH))[i];
        __syncthreads();
#pragma unroll
        for (int k = 0; k < 16; k++) {
            float4 w0 = *(const float4*)(sW + k * HH + cg);
            float4 w1 = *(const float4*)(sW + k * HH + cg + 4);
#pragma unroll
            for (int i = 0; i < 4; i++) {
                float m = sMT[(rb + 16 * i) * PITCH + kc + k];
                acc[i][0] += m * w0.x; acc[i][1] += m * w0.y;
                acc[i][2] += m * w0.z; acc[i][3] += m * w0.w;
                acc[i][4] += m * w1.x; acc[i][5] += m * w1.y;
                acc[i][6] += m * w1.z; acc[i][7] += m * w1.w;
            }
        }
    }
    __syncthreads();

    // t = relu(acc + b1) -> sMT
    {
        float4 b0 = *(const float4*)(B1 + cg);
        float4 b1 = *(const float4*)(B1 + cg + 4);
#pragma unroll
        for (int i = 0; i < 4; i++) {
            int r = rb + 16 * i;
            float4 t0, t1;
            t0.x = fmaxf(acc[i][0] + b0.x, 0.f);
            t0.y = fmaxf(acc[i][1] + b0.y, 0.f);
            t0.z = fmaxf(acc[i][2] + b0.z, 0.f);
            t0.w = fmaxf(acc[i][3] + b0.w, 0.f);
            t1.x = fmaxf(acc[i][4] + b1.x, 0.f);
            t1.y = fmaxf(acc[i][5] + b1.y, 0.f);
            t1.z = fmaxf(acc[i][6] + b1.z, 0.f);
            t1.w = fmaxf(acc[i][7] + b1.w, 0.f);
            *(float4*)(sMT + r * PITCH + cg)     = t0;
            *(float4*)(sMT + r * PITCH + cg + 4) = t1;
#pragma unroll
            for (int j = 0; j < 8; j++) acc[i][j] = 0.f;
        }
    }

    // ---- GEMM 2: o = t @ W2 ----
    for (int kc = 0; kc < HH; kc += 16) {
        __syncthreads();
        for (int i = tid; i < 16 * 32; i += 256)
            ((float4*)sW)[i] = ((const float4*)(W2 + (size_t)kc * HH))[i];
        __syncthreads();
#pragma unroll
        for (int k = 0; k < 16; k++) {
            float4 w0 = *(const float4*)(sW + k * HH + cg);
            float4 w1 = *(const float4*)(sW + k * HH + cg + 4);
#pragma unroll
            for (int i = 0; i < 4; i++) {
                float t = sMT[(rb + 16 * i) * PITCH + kc + k];
                acc[i][0] += t * w0.x; acc[i][1] += t * w0.y;
                acc[i][2] += t * w0.z; acc[i][3] += t * w0.w;
                acc[i][4] += t * w1.x; acc[i][5] += t * w1.y;
                acc[i][6] += t * w1.z; acc[i][7] += t * w1.w;
            }
        }
    }

    // h_out = relu(acc + b2)
    {
        float4 b0 = *(const float4*)(B2 + cg);
        float4 b1 = *(const float4*)(B2 + cg + 4);
#pragma unroll
        for (int i = 0; i < 4; i++) {
            int n = row0 + rb + 16 * i;
            if (n < NN) {
                float4 o0, o1;
                o0.x = fmaxf(acc[i][0] + b0.x, 0.f);
                o0.y = fmaxf(acc[i][1] + b0.y, 0.f);
                o0.z = fmaxf(acc[i][2] + b0.z, 0.f);
                o0.w = fmaxf(acc[i][3] + b0.w, 0.f);
                o1.x = fmaxf(acc[i][4] + b1.x, 0.f);
                o1.y = fmaxf(acc[i][5] + b1.y, 0.f);
                o1.z = fmaxf(acc[i][6] + b1.z, 0.f);
                o1.w = fmaxf(acc[i][7] + b1.w, 0.f);
                *(float4*)(h_out + (size_t)n * HH + cg)     = o0;
                *(float4*)(h_out + (size_t)n * HH + cg + 4) = o1;
            }
        }
    }
}

// ---------------------------------------------------------------------------
__global__ void pool_kernel(const float* __restrict__ h, const int* __restrict__ batch,
                            float* __restrict__ gsum, int* __restrict__ gcnt) {
    int n = (blockIdx.x * blockDim.x + threadIdx.x) >> 5;
    if (n >= NN) return;
    int lane = threadIdx.x & 31;
    int b = __ldg(batch + n);
    float4 v = ((const float4*)(h + (size_t)n * HH))[lane];
    float* dst = gsum + (size_t)b * HH + lane * 4;
    atomicAdd(dst + 0, v.x);
    atomicAdd(dst + 1, v.y);
    atomicAdd(dst + 2, v.z);
    atomicAdd(dst + 3, v.w);
    if (lane == 0) atomicAdd(gcnt + b, 1);
}

// ---------------------------------------------------------------------------
__global__ void head_kernel(const float* __restrict__ gsum, const int* __restrict__ gcnt,
                            const float* __restrict__ Ws, const float* __restrict__ Bs,
                            const float* __restrict__ ew, const float* __restrict__ eb,
                            const float* __restrict__ dw, const float* __restrict__ db,
                            float* __restrict__ out) {
    int g = blockIdx.x;
    int j = threadIdx.x;
    __shared__ float sg[HH];
    __shared__ float re[HH];
    __shared__ float rd[HH];

    float cnt = fmaxf((float)gcnt[g], 1.f);
    sg[j] = gsum[(size_t)g * HH + j] / cnt;
    __syncthreads();

    float a = Bs[j];
#pragma unroll 8
    for (int k = 0; k < HH; k++) a += sg[k] * Ws[k * HH + j];
    a = fmaxf(a, 0.f);

    re[j] = a * ew[j];
    rd[j] = a * dw[j];
    __syncthreads();
    for (int s = 64; s > 0; s >>= 1) {
        if (j < s) { re[j] += re[j + s]; rd[j] += rd[j + s]; }
        __syncthreads();
    }
    if (j == 0) {
        out[g]      = re[0] + eb[0];
        out[GG + g] = rd[0] + db[0];
    }
}

// ---------------------------------------------------------------------------
extern "C" void kernel_launch(void* const* d_in, const int* in_sizes, int n_in,
                              void* d_out, int out_size) {
    const float* x       = (const float*)d_in[0];
    const int*   ei      = (const int*)  d_in[1];
    const int*   batch   = (const int*)  d_in[2];
    const float* proj_w  = (const float*)d_in[3];
    const float* proj_b  = (const float*)d_in[4];
    const float* conv_w1 = (const float*)d_in[5];
    const float* conv_b1 = (const float*)d_in[6];
    const float* conv_w2 = (const float*)d_in[7];
    const float* conv_b2 = (const float*)d_in[8];
    const float* sh_w    = (const float*)d_in[9];
    const float* sh_b    = (const float*)d_in[10];
    const float* e_w     = (const float*)d_in[11];
    const float* e_b     = (const float*)d_in[12];
    const float* d_w     = (const float*)d_in[13];
    const float* d_b     = (const float*)d_in[14];
    float* out = (float*)d_out;

    float *h, *h2, *m, *gsum;
    int *off, *cur, *csr, *bsum, *bpre, *gcnt;
    cudaGetSymbolAddress((void**)&h,    g_h);
    cudaGetSymbolAddress((void**)&h2,   g_h2);
    cudaGetSymbolAddress((void**)&m,    g_m);
    cudaGetSymbolAddress((void**)&off,  g_off);
    cudaGetSymbolAddress((void**)&cur,  g_cur);
    cudaGetSymbolAddress((void**)&csr,  g_csr);
    cudaGetSymbolAddress((void**)&bsum, g_bsum);
    cudaGetSymbolAddress((void**)&bpre, g_bpre);
    cudaGetSymbolAddress((void**)&gsum, g_gsum);
    cudaGetSymbolAddress((void**)&gcnt, g_gcnt);

    // input projection
    proj_kernel<<<NN, HH>>>(x, proj_w, proj_b, h);

    // CSR build (edges grouped by destination); deg accumulates in off[]
    zero_kernel<<<(GG * HH + 255) / 256, 256>>>(off, gsum, gcnt);
    hist_kernel<<<(EE + 255) / 256, 256>>>(ei, off);
    scan1_kernel<<<SCAN_NB, SCAN_B>>>(off, bsum);
    scan2_kernel<<<1, 256>>>(bsum, bpre);
    scan3_kernel<<<(NN + 256) / 256, 256>>>(off, bpre, cur);
    fill_kernel<<<(EE + 255) / 256, 256>>>(ei, cur, csr);

    // GIN layers (ping-pong h <-> h2; m is the aggregation scratch)
    const int gat_blocks = (NN * 32 + 255) / 256;
    const int mlp_blocks = (NN + 63) / 64;
    const float* src = h;
    float* dst = h2;
    for (int l = 0; l < LL; l++) {
        gather_kernel<<<gat_blocks, 256>>>(src, m, off, csr);
        mlp_kernel<<<mlp_blocks, 256>>>(m, dst,
                                        conv_w1 + (size_t)l * HH * HH,
                                        conv_b1 + (size_t)l * HH,
                                        conv_w2 + (size_t)l * HH * HH,
                                        conv_b2 + (size_t)l * HH);
        const float* t = dst; dst = (float*)src; src = t;
    }
    const float* hf = src;   // final features

    pool_kernel<<<(NN * 32 + 255) / 256, 256>>>(hf, batch, gsum, gcnt);
    head_kernel<<<GG, HH>>>(gsum, gcnt, sh_w, sh_b, e_w, e_b, d_w, d_b, out);
}

// round 6
// speedup vs baseline: 1.0692x; 1.0692x over previous
#include <cuda_runtime.h>
#include <cuda_bf16.h>

#define NN 100000
#define EE 1600000
#define GG 2000
#define HH 128
#define LL 3
#define SCAN_B 512
#define SCAN_NB ((NN + SCAN_B - 1) / SCAN_B)   // 196
#define PITCH 132   // 4*PITCH % 32 == 16 -> row-pairs 4 apart hit different banks

// Scratch (__device__ globals; no allocations allowed)
__device__ float g_h [NN * HH];
__device__ float g_h2[NN * HH];
__device__ int   g_off[NN + 1];
__device__ int   g_cur[NN];
__device__ int   g_csr[EE];
__device__ int   g_bsum[256];
__device__ int   g_bpre[256];
__device__ float g_gsum[GG * HH];
__device__ int   g_gcnt[GG];

// ---------------------------------------------------------------------------
__global__ void proj_kernel(const float* __restrict__ x,
                            const float* __restrict__ pw,
                            const float* __restrict__ pb,
                            float* __restrict__ h) {
    int n = blockIdx.x;
    int j = threadIdx.x;
    const float* xr = x + (size_t)n * 4;
    float acc = pb[j];
    acc += xr[0] * pw[0 * HH + j];
    acc += xr[1] * pw[1 * HH + j];
    acc += xr[2] * pw[2 * HH + j];
    acc += xr[3] * pw[3 * HH + j];
    h[(size_t)n * HH + j] = acc;
}

// ---------------------------------------------------------------------------
__global__ void zero_kernel(int* __restrict__ deg,
                            float* __restrict__ gsum, int* __restrict__ gcnt) {
    int i = blockIdx.x * blockDim.x + threadIdx.x;
    if (i <= NN) deg[i] = 0;
    if (i < GG * HH) gsum[i] = 0.f;
    if (i < GG) gcnt[i] = 0;
}

__global__ void hist_kernel(const int* __restrict__ ei, int* __restrict__ deg) {
    int e = blockIdx.x * blockDim.x + threadIdx.x;
    if (e < EE) atomicAdd(deg + __ldg(ei + EE + e), 1);
}

__global__ void scan1_kernel(int* __restrict__ off, int* __restrict__ bsum) {
    __shared__ int s[SCAN_B];
    int t = threadIdx.x;
    int i = blockIdx.x * SCAN_B + t;
    int v = (i < NN) ? off[i] : 0;
    s[t] = v;
    __syncthreads();
    for (int o = 1; o < SCAN_B; o <<= 1) {
        int x = (t >= o) ? s[t - o] : 0;
        __syncthreads();
        s[t] += x;
        __syncthreads();
    }
    if (i < NN) off[i] = s[t] - v;
    if (t == SCAN_B - 1) bsum[blockIdx.x] = s[t];
}

__global__ void scan2_kernel(const int* __restrict__ bsum, int* __restrict__ bpre) {
    __shared__ int s[256];
    int t = threadIdx.x;
    int v = (t < SCAN_NB) ? bsum[t] : 0;
    s[t] = v;
    __syncthreads();
    for (int o = 1; o < 256; o <<= 1) {
        int x = (t >= o) ? s[t - o] : 0;
        __syncthreads();
        s[t] += x;
        __syncthreads();
    }
    if (t < SCAN_NB) bpre[t] = s[t] - v;
}

__global__ void scan3_kernel(int* __restrict__ off, const int* __restrict__ bpre,
                             int* __restrict__ cur) {
    int i = blockIdx.x * blockDim.x + threadIdx.x;
    if (i < NN) {
        int o = off[i] + bpre[i / SCAN_B];
        off[i] = o;
        cur[i] = o;
    }
    if (i == NN) off[NN] = EE;
}

__global__ void fill_kernel(const int* __restrict__ ei,
                            int* __restrict__ cur, int* __restrict__ csr) {
    int e = blockIdx.x * blockDim.x + threadIdx.x;
    if (e < EE) {
        int s = __ldg(ei + e);
        int d = __ldg(ei + EE + e);
        int p = atomicAdd(cur + d, 1);
        csr[p] = s;
    }
}

// ---------------------------------------------------------------------------
// Fused: gather (m = h + sum_nbr h) into smem tile, then
//        h_out = relu( relu(m @ W1 + b1) @ W2 + b2 )
// 64-row tile, 256 threads.
// Gather: warp w handles rows w*8..w*8+7; lane l owns float4 chunk l (full
// 512B row per load instruction -> perfectly coalesced; unroll 4 -> MLP 4).
// GEMM: thread (rb=tid>>4, cg=(tid&15)*8) owns rows rb*4+i (i<4),
// cols cg..cg+7 -> acc[4][8]. Within a warp the two rb values give m
// addresses 4*PITCH=528 floats apart = bank distance 16 -> conflict-free
// dual-broadcast. W row reads are float4, conflict-free.
__global__ void __launch_bounds__(256) mlp_fused_kernel(
    const float* __restrict__ in, float* __restrict__ out,
    const int* __restrict__ off, const int* __restrict__ csr,
    const float* __restrict__ W1, const float* __restrict__ B1,
    const float* __restrict__ W2, const float* __restrict__ B2) {
    __shared__ float sMT[64 * PITCH];
    __shared__ float sW[16 * HH];

    int tid  = threadIdx.x;
    int lane = tid & 31;
    int wrp  = tid >> 5;
    int row0 = blockIdx.x * 64;
    const float4* in4 = (const float4*)in;

    // ---- gather phase ----
#pragma unroll
    for (int j = 0; j < 8; j++) {
        int r = wrp * 8 + j;
        int n = row0 + r;
        float4 a = make_float4(0.f, 0.f, 0.f, 0.f);
        if (n < NN) {
            a = __ldg(in4 + (size_t)n * 32 + lane);
            int e0 = __ldg(off + n);
            int e1 = __ldg(off + n + 1);
#pragma unroll 4
            for (int e = e0; e < e1; e++) {
                int s = __ldg(csr + e);
                float4 v = __ldg(in4 + (size_t)s * 32 + lane);
                a.x += v.x; a.y += v.y; a.z += v.z; a.w += v.w;
            }
        }
        *(float4*)(sMT + r * PITCH + lane * 4) = a;
    }

    int rb = tid >> 4;            // 0..15  -> rows rb*4 .. rb*4+3
    int cg = (tid & 15) * 8;      // 0..120 step 8

    float acc[4][8];
#pragma unroll
    for (int i = 0; i < 4; i++)
#pragma unroll
        for (int j = 0; j < 8; j++) acc[i][j] = 0.f;

    // ---- GEMM 1: t = m @ W1 ----
    for (int kc = 0; kc < HH; kc += 16) {
        __syncthreads();
        for (int i = tid; i < 16 * 32; i += 256)
            ((float4*)sW)[i] = ((const float4*)(W1 + (size_t)kc * HH))[i];
        __syncthreads();
#pragma unroll
        for (int k = 0; k < 16; k++) {
            float4 w0 = *(const float4*)(sW + k * HH + cg);
            float4 w1 = *(const float4*)(sW + k * HH + cg + 4);
#pragma unroll
            for (int i = 0; i < 4; i++) {
                float m = sMT[(rb * 4 + i) * PITCH + kc + k];
                acc[i][0] += m * w0.x; acc[i][1] += m * w0.y;
                acc[i][2] += m * w0.z; acc[i][3] += m * w0.w;
                acc[i][4] += m * w1.x; acc[i][5] += m * w1.y;
                acc[i][6] += m * w1.z; acc[i][7] += m * w1.w;
            }
        }
    }
    __syncthreads();

    // t = relu(acc + b1) -> sMT
    {
        float4 b0 = *(const float4*)(B1 + cg);
        float4 b1 = *(const float4*)(B1 + cg + 4);
#pragma unroll
        for (int i = 0; i < 4; i++) {
            int r = rb * 4 + i;
            float4 t0, t1;
            t0.x = fmaxf(acc[i][0] + b0.x, 0.f);
            t0.y = fmaxf(acc[i][1] + b0.y, 0.f);
            t0.z = fmaxf(acc[i][2] + b0.z, 0.f);
            t0.w = fmaxf(acc[i][3] + b0.w, 0.f);
            t1.x = fmaxf(acc[i][4] + b1.x, 0.f);
            t1.y = fmaxf(acc[i][5] + b1.y, 0.f);
            t1.z = fmaxf(acc[i][6] + b1.z, 0.f);
            t1.w = fmaxf(acc[i][7] + b1.w, 0.f);
            *(float4*)(sMT + r * PITCH + cg)     = t0;
            *(float4*)(sMT + r * PITCH + cg + 4) = t1;
#pragma unroll
            for (int j = 0; j < 8; j++) acc[i][j] = 0.f;
        }
    }

    // ---- GEMM 2: o = t @ W2 ----
    for (int kc = 0; kc < HH; kc += 16) {
        __syncthreads();
        for (int i = tid; i < 16 * 32; i += 256)
            ((float4*)sW)[i] = ((const float4*)(W2 + (size_t)kc * HH))[i];
        __syncthreads();
#pragma unroll
        for (int k = 0; k < 16; k++) {
            float4 w0 = *(const float4*)(sW + k * HH + cg);
            float4 w1 = *(const float4*)(sW + k * HH + cg + 4);
#pragma unroll
            for (int i = 0; i < 4; i++) {
                float t = sMT[(rb * 4 + i) * PITCH + kc + k];
                acc[i][0] += t * w0.x; acc[i][1] += t * w0.y;
                acc[i][2] += t * w0.z; acc[i][3] += t * w0.w;
                acc[i][4] += t * w1.x; acc[i][5] += t * w1.y;
                acc[i][6] += t * w1.z; acc[i][7] += t * w1.w;
            }
        }
    }

    // h_out = relu(acc + b2)
    {
        float4 b0 = *(const float4*)(B2 + cg);
        float4 b1 = *(const float4*)(B2 + cg + 4);
#pragma unroll
        for (int i = 0; i < 4; i++) {
            int n = row0 + rb * 4 + i;
            if (n < NN) {
                float4 o0, o1;
                o0.x = fmaxf(acc[i][0] + b0.x, 0.f);
                o0.y = fmaxf(acc[i][1] + b0.y, 0.f);
                o0.z = fmaxf(acc[i][2] + b0.z, 0.f);
                o0.w = fmaxf(acc[i][3] + b0.w, 0.f);
                o1.x = fmaxf(acc[i][4] + b1.x, 0.f);
                o1.y = fmaxf(acc[i][5] + b1.y, 0.f);
                o1.z = fmaxf(acc[i][6] + b1.z, 0.f);
                o1.w = fmaxf(acc[i][7] + b1.w, 0.f);
                *(float4*)(out + (size_t)n * HH + cg)     = o0;
                *(float4*)(out + (size_t)n * HH + cg + 4) = o1;
            }
        }
    }
}

// ---------------------------------------------------------------------------
__global__ void pool_kernel(const float* __restrict__ h, const int* __restrict__ batch,
                            float* __restrict__ gsum, int* __restrict__ gcnt) {
    int n = (blockIdx.x * blockDim.x + threadIdx.x) >> 5;
    if (n >= NN) return;
    int lane = threadIdx.x & 31;
    int b = __ldg(batch + n);
    float4 v = ((const float4*)(h + (size_t)n * HH))[lane];
    float* dst = gsum + (size_t)b * HH + lane * 4;
    atomicAdd(dst + 0, v.x);
    atomicAdd(dst + 1, v.y);
    atomicAdd(dst + 2, v.z);
    atomicAdd(dst + 3, v.w);
    if (lane == 0) atomicAdd(gcnt + b, 1);
}

// ---------------------------------------------------------------------------
__global__ void head_kernel(const float* __restrict__ gsum, const int* __restrict__ gcnt,
                            const float* __restrict__ Ws, const float* __restrict__ Bs,
                            const float* __restrict__ ew, const float* __restrict__ eb,
                            const float* __restrict__ dw, const float* __restrict__ db,
                            float* __restrict__ out) {
    int g = blockIdx.x;
    int j = threadIdx.x;
    __shared__ float sg[HH];
    __shared__ float re[HH];
    __shared__ float rd[HH];

    float cnt = fmaxf((float)gcnt[g], 1.f);
    sg[j] = gsum[(size_t)g * HH + j] / cnt;
    __syncthreads();

    float a = Bs[j];
#pragma unroll 8
    for (int k = 0; k < HH; k++) a += sg[k] * Ws[k * HH + j];
    a = fmaxf(a, 0.f);

    re[j] = a * ew[j];
    rd[j] = a * dw[j];
    __syncthreads();
    for (int s = 64; s > 0; s >>= 1) {
        if (j < s) { re[j] += re[j + s]; rd[j] += rd[j + s]; }
        __syncthreads();
    }
    if (j == 0) {
        out[g]      = re[0] + eb[0];
        out[GG + g] = rd[0] + db[0];
    }
}

// ---------------------------------------------------------------------------
extern "C" void kernel_launch(void* const* d_in, const int* in_sizes, int n_in,
                              void* d_out, int out_size) {
    const float* x       = (const float*)d_in[0];
    const int*   ei      = (const int*)  d_in[1];
    const int*   batch   = (const int*)  d_in[2];
    const float* proj_w  = (const float*)d_in[3];
    const float* proj_b  = (const float*)d_in[4];
    const float* conv_w1 = (const float*)d_in[5];
    const float* conv_b1 = (const float*)d_in[6];
    const float* conv_w2 = (const float*)d_in[7];
    const float* conv_b2 = (const float*)d_in[8];
    const float* sh_w    = (const float*)d_in[9];
    const float* sh_b    = (const float*)d_in[10];
    const float* e_w     = (const float*)d_in[11];
    const float* e_b     = (const float*)d_in[12];
    const float* d_w     = (const float*)d_in[13];
    const float* d_b     = (const float*)d_in[14];
    float* out = (float*)d_out;

    float *h, *h2, *gsum;
    int *off, *cur, *csr, *bsum, *bpre, *gcnt;
    cudaGetSymbolAddress((void**)&h,    g_h);
    cudaGetSymbolAddress((void**)&h2,   g_h2);
    cudaGetSymbolAddress((void**)&off,  g_off);
    cudaGetSymbolAddress((void**)&cur,  g_cur);
    cudaGetSymbolAddress((void**)&csr,  g_csr);
    cudaGetSymbolAddress((void**)&bsum, g_bsum);
    cudaGetSymbolAddress((void**)&bpre, g_bpre);
    cudaGetSymbolAddress((void**)&gsum, g_gsum);
    cudaGetSymbolAddress((void**)&gcnt, g_gcnt);

    // input projection
    proj_kernel<<<NN, HH>>>(x, proj_w, proj_b, h);

    // CSR build (edges grouped by destination); deg accumulates in off[]
    zero_kernel<<<(GG * HH + 255) / 256, 256>>>(off, gsum, gcnt);
    hist_kernel<<<(EE + 255) / 256, 256>>>(ei, off);
    scan1_kernel<<<SCAN_NB, SCAN_B>>>(off, bsum);
    scan2_kernel<<<1, 256>>>(bsum, bpre);
    scan3_kernel<<<(NN + 256) / 256, 256>>>(off, bpre, cur);
    fill_kernel<<<(EE + 255) / 256, 256>>>(ei, cur, csr);

    // GIN layers (fused gather+MLP; ping-pong h <-> h2)
    const int mlp_blocks = (NN + 63) / 64;
    const float* src = h;
    float* dst = h2;
    for (int l = 0; l < LL; l++) {
        mlp_fused_kernel<<<mlp_blocks, 256>>>(src, dst, off, csr,
                                              conv_w1 + (size_t)l * HH * HH,
                                              conv_b1 + (size_t)l * HH,
                                              conv_w2 + (size_t)l * HH * HH,
                                              conv_b2 + (size_t)l * HH);
        const float* t = dst; dst = (float*)src; src = t;
    }
    const float* hf = src;   // final features

    pool_kernel<<<(NN * 32 + 255) / 256, 256>>>(hf, batch, gsum, gcnt);
    head_kernel<<<GG, HH>>>(gsum, gcnt, sh_w, sh_b, e_w, e_b, d_w, d_b, out);
}

// round 7
// speedup vs baseline: 1.0892x; 1.0187x over previous
#include <cuda_runtime.h>
#include <cuda_bf16.h>

#define NN 100000
#define EE 1600000
#define GG 2000
#define HH 128
#define LL 3
#define SCAN_B 512
#define SCAN_NB ((NN + SCAN_B - 1) / SCAN_B)   // 196
#define PITCH 132   // 4*PITCH % 32 == 16 -> row-groups 4 apart hit different banks

// Scratch (__device__ globals; no allocations allowed)
__device__ float g_h [NN * HH];
__device__ float g_h2[NN * HH];
__device__ int   g_off[NN + 1];
__device__ int   g_cur[NN];
__device__ int   g_csr[EE];
__device__ int   g_bsum[256];
__device__ int   g_bpre[256];
__device__ float g_gsum[GG * HH];
__device__ int   g_gcnt[GG];

// ---------------------------------------------------------------------------
__global__ void proj_kernel(const float* __restrict__ x,
                            const float* __restrict__ pw,
                            const float* __restrict__ pb,
                            float* __restrict__ h) {
    int n = blockIdx.x;
    int j = threadIdx.x;
    const float* xr = x + (size_t)n * 4;
    float acc = pb[j];
    acc += xr[0] * pw[0 * HH + j];
    acc += xr[1] * pw[1 * HH + j];
    acc += xr[2] * pw[2 * HH + j];
    acc += xr[3] * pw[3 * HH + j];
    h[(size_t)n * HH + j] = acc;
}

// ---------------------------------------------------------------------------
__global__ void zero_kernel(int* __restrict__ deg,
                            float* __restrict__ gsum, int* __restrict__ gcnt) {
    int i = blockIdx.x * blockDim.x + threadIdx.x;
    if (i <= NN) deg[i] = 0;
    if (i < GG * HH) gsum[i] = 0.f;
    if (i < GG) gcnt[i] = 0;
}

__global__ void hist_kernel(const int* __restrict__ ei, int* __restrict__ deg) {
    int e = blockIdx.x * blockDim.x + threadIdx.x;
    if (e < EE) atomicAdd(deg + __ldg(ei + EE + e), 1);
}

__global__ void scan1_kernel(int* __restrict__ off, int* __restrict__ bsum) {
    __shared__ int s[SCAN_B];
    int t = threadIdx.x;
    int i = blockIdx.x * SCAN_B + t;
    int v = (i < NN) ? off[i] : 0;
    s[t] = v;
    __syncthreads();
    for (int o = 1; o < SCAN_B; o <<= 1) {
        int x = (t >= o) ? s[t - o] : 0;
        __syncthreads();
        s[t] += x;
        __syncthreads();
    }
    if (i < NN) off[i] = s[t] - v;
    if (t == SCAN_B - 1) bsum[blockIdx.x] = s[t];
}

__global__ void scan2_kernel(const int* __restrict__ bsum, int* __restrict__ bpre) {
    __shared__ int s[256];
    int t = threadIdx.x;
    int v = (t < SCAN_NB) ? bsum[t] : 0;
    s[t] = v;
    __syncthreads();
    for (int o = 1; o < 256; o <<= 1) {
        int x = (t >= o) ? s[t - o] : 0;
        __syncthreads();
        s[t] += x;
        __syncthreads();
    }
    if (t < SCAN_NB) bpre[t] = s[t] - v;
}

__global__ void scan3_kernel(int* __restrict__ off, const int* __restrict__ bpre,
                             int* __restrict__ cur) {
    int i = blockIdx.x * blockDim.x + threadIdx.x;
    if (i < NN) {
        int o = off[i] + bpre[i / SCAN_B];
        off[i] = o;
        cur[i] = o;
    }
    if (i == NN) off[NN] = EE;
}

__global__ void fill_kernel(const int* __restrict__ ei,
                            int* __restrict__ cur, int* __restrict__ csr) {
    int e = blockIdx.x * blockDim.x + threadIdx.x;
    if (e < EE) {
        int s = __ldg(ei + e);
        int d = __ldg(ei + EE + e);
        int p = atomicAdd(cur + d, 1);
        csr[p] = s;
    }
}

// ---------------------------------------------------------------------------
// Fused: gather (m = h + sum_nbr h) into smem tile, then
//        h_out = relu( relu(m @ W1 + b1) @ W2 + b2 )
// 64-row tile, 256 threads, min 4 CTAs/SM (reg cap 64 for overlap).
// Gather: warp w handles rows w*8..w*8+7 as 4 interleaved PAIRS (double MLP);
// the merged edge loop branches are warp-uniform (deg is per-row).
// GEMM: thread (rb=tid>>4, cg=(tid&15)*8) owns rows rb*4+i (i<4),
// cols cg..cg+7 -> acc[4][8]; dual m-broadcast lands in different banks.
__global__ void __launch_bounds__(256, 4) mlp_fused_kernel(
    const float* __restrict__ in, float* __restrict__ out,
    const int* __restrict__ off, const int* __restrict__ csr,
    const float* __restrict__ W1, const float* __restrict__ B1,
    const float* __restrict__ W2, const float* __restrict__ B2) {
    __shared__ float sMT[64 * PITCH];
    __shared__ float sW[16 * HH];

    int tid  = threadIdx.x;
    int lane = tid & 31;
    int wrp  = tid >> 5;
    int row0 = blockIdx.x * 64;
    const float4* in4 = (const float4*)in;

    // ---- gather phase: 4 pairs of rows, interleaved edge loops ----
#pragma unroll
    for (int jj = 0; jj < 4; jj++) {
        int r0 = wrp * 8 + jj * 2;
        int n0 = row0 + r0;
        int n1 = n0 + 1;
        float4 a0 = make_float4(0.f, 0.f, 0.f, 0.f);
        float4 a1 = make_float4(0.f, 0.f, 0.f, 0.f);
        int d0 = 0, d1 = 0, s0 = 0, s1 = 0;
        if (n0 < NN) {
            a0 = __ldg(in4 + (size_t)n0 * 32 + lane);
            s0 = __ldg(off + n0);
            d0 = __ldg(off + n0 + 1) - s0;
        }
        if (n1 < NN) {
            a1 = __ldg(in4 + (size_t)n1 * 32 + lane);
            s1 = __ldg(off + n1);
            d1 = __ldg(off + n1 + 1) - s1;
        }
        int dmax = d0 > d1 ? d0 : d1;
#pragma unroll 4
        for (int e = 0; e < dmax; e++) {
            if (e < d0) {            // warp-uniform branch
                int s = __ldg(csr + s0 + e);
                float4 v = __ldg(in4 + (size_t)s * 32 + lane);
                a0.x += v.x; a0.y += v.y; a0.z += v.z; a0.w += v.w;
            }
            if (e < d1) {            // warp-uniform branch
                int s = __ldg(csr + s1 + e);
                float4 v = __ldg(in4 + (size_t)s * 32 + lane);
                a1.x += v.x; a1.y += v.y; a1.z += v.z; a1.w += v.w;
            }
        }
        *(float4*)(sMT + r0 * PITCH + lane * 4)       = a0;
        *(float4*)(sMT + (r0 + 1) * PITCH + lane * 4) = a1;
    }

    int rb = tid >> 4;            // 0..15  -> rows rb*4 .. rb*4+3
    int cg = (tid & 15) * 8;      // 0..120 step 8

    float acc[4][8];
#pragma unroll
    for (int i = 0; i < 4; i++)
#pragma unroll
        for (int j = 0; j < 8; j++) acc[i][j] = 0.f;

    // ---- GEMM 1: t = m @ W1 ----
    for (int kc = 0; kc < HH; kc += 16) {
        __syncthreads();
        for (int i = tid; i < 16 * 32; i += 256)
            ((float4*)sW)[i] = ((const float4*)(W1 + (size_t)kc * HH))[i];
        __syncthreads();
#pragma unroll
        for (int k = 0; k < 16; k++) {
            float4 w0 = *(const float4*)(sW + k * HH + cg);
            float4 w1 = *(const float4*)(sW + k * HH + cg + 4);
#pragma unroll
            for (int i = 0; i < 4; i++) {
                float m = sMT[(rb * 4 + i) * PITCH + kc + k];
                acc[i][0] += m * w0.x; acc[i][1] += m * w0.y;
                acc[i][2] += m * w0.z; acc[i][3] += m * w0.w;
                acc[i][4] += m * w1.x; acc[i][5] += m * w1.y;
                acc[i][6] += m * w1.z; acc[i][7] += m * w1.w;
            }
        }
    }
    __syncthreads();

    // t = relu(acc + b1) -> sMT
    {
        float4 b0 = *(const float4*)(B1 + cg);
        float4 b1 = *(const float4*)(B1 + cg + 4);
#pragma unroll
        for (int i = 0; i < 4; i++) {
            int r = rb * 4 + i;
            float4 t0, t1;
            t0.x = fmaxf(acc[i][0] + b0.x, 0.f);
            t0.y = fmaxf(acc[i][1] + b0.y, 0.f);
            t0.z = fmaxf(acc[i][2] + b0.z, 0.f);
            t0.w = fmaxf(acc[i][3] + b0.w, 0.f);
            t1.x = fmaxf(acc[i][4] + b1.x, 0.f);
            t1.y = fmaxf(acc[i][5] + b1.y, 0.f);
            t1.z = fmaxf(acc[i][6] + b1.z, 0.f);
            t1.w = fmaxf(acc[i][7] + b1.w, 0.f);
            *(float4*)(sMT + r * PITCH + cg)     = t0;
            *(float4*)(sMT + r * PITCH + cg + 4) = t1;
#pragma unroll
            for (int j = 0; j < 8; j++) acc[i][j] = 0.f;
        }
    }

    // ---- GEMM 2: o = t @ W2 ----
    for (int kc = 0; kc < HH; kc += 16) {
        __syncthreads();
        for (int i = tid; i < 16 * 32; i += 256)
            ((float4*)sW)[i] = ((const float4*)(W2 + (size_t)kc * HH))[i];
        __syncthreads();
#pragma unroll
        for (int k = 0; k < 16; k++) {
            float4 w0 = *(const float4*)(sW + k * HH + cg);
            float4 w1 = *(const float4*)(sW + k * HH + cg + 4);
#pragma unroll
            for (int i = 0; i < 4; i++) {
                float t = sMT[(rb * 4 + i) * PITCH + kc + k];
                acc[i][0] += t * w0.x; acc[i][1] += t * w0.y;
                acc[i][2] += t * w0.z; acc[i][3] += t * w0.w;
                acc[i][4] += t * w1.x; acc[i][5] += t * w1.y;
                acc[i][6] += t * w1.z; acc[i][7] += t * w1.w;
            }
        }
    }

    // h_out = relu(acc + b2)
    {
        float4 b0 = *(const float4*)(B2 + cg);
        float4 b1 = *(const float4*)(B2 + cg + 4);
#pragma unroll
        for (int i = 0; i < 4; i++) {
            int n = row0 + rb * 4 + i;
            if (n < NN) {
                float4 o0, o1;
                o0.x = fmaxf(acc[i][0] + b0.x, 0.f);
                o0.y = fmaxf(acc[i][1] + b0.y, 0.f);
                o0.z = fmaxf(acc[i][2] + b0.z, 0.f);
                o0.w = fmaxf(acc[i][3] + b0.w, 0.f);
                o1.x = fmaxf(acc[i][4] + b1.x, 0.f);
                o1.y = fmaxf(acc[i][5] + b1.y, 0.f);
                o1.z = fmaxf(acc[i][6] + b1.z, 0.f);
                o1.w = fmaxf(acc[i][7] + b1.w, 0.f);
                *(float4*)(out + (size_t)n * HH + cg)     = o0;
                *(float4*)(out + (size_t)n * HH + cg + 4) = o1;
            }
        }
    }
}

// ---------------------------------------------------------------------------
__global__ void pool_kernel(const float* __restrict__ h, const int* __restrict__ batch,
                            float* __restrict__ gsum, int* __restrict__ gcnt) {
    int n = (blockIdx.x * blockDim.x + threadIdx.x) >> 5;
    if (n >= NN) return;
    int lane = threadIdx.x & 31;
    int b = __ldg(batch + n);
    float4 v = ((const float4*)(h + (size_t)n * HH))[lane];
    float* dst = gsum + (size_t)b * HH + lane * 4;
    atomicAdd(dst + 0, v.x);
    atomicAdd(dst + 1, v.y);
    atomicAdd(dst + 2, v.z);
    atomicAdd(dst + 3, v.w);
    if (lane == 0) atomicAdd(gcnt + b, 1);
}

// ---------------------------------------------------------------------------
__global__ void head_kernel(const float* __restrict__ gsum, const int* __restrict__ gcnt,
                            const float* __restrict__ Ws, const float* __restrict__ Bs,
                            const float* __restrict__ ew, const float* __restrict__ eb,
                            const float* __restrict__ dw, const float* __restrict__ db,
                            float* __restrict__ out) {
    int g = blockIdx.x;
    int j = threadIdx.x;
    __shared__ float sg[HH];
    __shared__ float re[HH];
    __shared__ float rd[HH];

    float cnt = fmaxf((float)gcnt[g], 1.f);
    sg[j] = gsum[(size_t)g * HH + j] / cnt;
    __syncthreads();

    float a = Bs[j];
#pragma unroll 8
    for (int k = 0; k < HH; k++) a += sg[k] * Ws[k * HH + j];
    a = fmaxf(a, 0.f);

    re[j] = a * ew[j];
    rd[j] = a * dw[j];
    __syncthreads();
    for (int s = 64; s > 0; s >>= 1) {
        if (j < s) { re[j] += re[j + s]; rd[j] += rd[j + s]; }
        __syncthreads();
    }
    if (j == 0) {
        out[g]      = re[0] + eb[0];
        out[GG + g] = rd[0] + db[0];
    }
}

// ---------------------------------------------------------------------------
extern "C" void kernel_launch(void* const* d_in, const int* in_sizes, int n_in,
                              void* d_out, int out_size) {
    const float* x       = (const float*)d_in[0];
    const int*   ei      = (const int*)  d_in[1];
    const int*   batch   = (const int*)  d_in[2];
    const float* proj_w  = (const float*)d_in[3];
    const float* proj_b  = (const float*)d_in[4];
    const float* conv_w1 = (const float*)d_in[5];
    const float* conv_b1 = (const float*)d_in[6];
    const float* conv_w2 = (const float*)d_in[7];
    const float* conv_b2 = (const float*)d_in[8];
    const float* sh_w    = (const float*)d_in[9];
    const float* sh_b    = (const float*)d_in[10];
    const float* e_w     = (const float*)d_in[11];
    const float* e_b     = (const float*)d_in[12];
    const float* d_w     = (const float*)d_in[13];
    const float* d_b     = (const float*)d_in[14];
    float* out = (float*)d_out;

    float *h, *h2, *gsum;
    int *off, *cur, *csr, *bsum, *bpre, *gcnt;
    cudaGetSymbolAddress((void**)&h,    g_h);
    cudaGetSymbolAddress((void**)&h2,   g_h2);
    cudaGetSymbolAddress((void**)&off,  g_off);
    cudaGetSymbolAddress((void**)&cur,  g_cur);
    cudaGetSymbolAddress((void**)&csr,  g_csr);
    cudaGetSymbolAddress((void**)&bsum, g_bsum);
    cudaGetSymbolAddress((void**)&bpre, g_bpre);
    cudaGetSymbolAddress((void**)&gsum, g_gsum);
    cudaGetSymbolAddress((void**)&gcnt, g_gcnt);

    // input projection
    proj_kernel<<<NN, HH>>>(x, proj_w, proj_b, h);

    // CSR build (edges grouped by destination); deg accumulates in off[]
    zero_kernel<<<(GG * HH + 255) / 256, 256>>>(off, gsum, gcnt);
    hist_kernel<<<(EE + 255) / 256, 256>>>(ei, off);
    scan1_kernel<<<SCAN_NB, SCAN_B>>>(off, bsum);
    scan2_kernel<<<1, 256>>>(bsum, bpre);
    scan3_kernel<<<(NN + 256) / 256, 256>>>(off, bpre, cur);
    fill_kernel<<<(EE + 255) / 256, 256>>>(ei, cur, csr);

    // GIN layers (fused gather+MLP; ping-pong h <-> h2)
    const int mlp_blocks = (NN + 63) / 64;
    const float* src = h;
    float* dst = h2;
    for (int l = 0; l < LL; l++) {
        mlp_fused_kernel<<<mlp_blocks, 256>>>(src, dst, off, csr,
                                              conv_w1 + (size_t)l * HH * HH,
                                              conv_b1 + (size_t)l * HH,
                                              conv_w2 + (size_t)l * HH * HH,
                                              conv_b2 + (size_t)l * HH);
        const float* t = dst; dst = (float*)src; src = t;
    }
    const float* hf = src;   // final features

    pool_kernel<<<(NN * 32 + 255) / 256, 256>>>(hf, batch, gsum, gcnt);
    head_kernel<<<GG, HH>>>(gsum, gcnt, sh_w, sh_b, e_w, e_b, d_w, d_b, out);
}